// round 7
// baseline (speedup 1.0000x reference)
#include <cuda_runtime.h>
#include <cuda_bf16.h>
#include <mma.h>
#include <math.h>
#include <stdint.h>

using namespace nvcuda;

#define T_STEPS 1024
#define BATCH   256
#define E_DIM   128

__device__ float g_xproj[134217728];

// ---------------------------------------------------------------------------
// Kernel 1: x_proj = x @ W_ih^T + (b_ih + b_hh), tf32 wmma (validated).
// ---------------------------------------------------------------------------
__global__ __launch_bounds__(256, 2)
void xproj_gemm_tf32(const float* __restrict__ A,
                     const float* __restrict__ W,
                     const float* __restrict__ bih,
                     const float* __restrict__ bhh)
{
    constexpr int AP = 36;
    __shared__ float As[128 * AP];
    __shared__ float Bs[128 * AP];
    __shared__ float BiasT[16 * 132];

    const int n0  = blockIdx.x * 128;
    const int m0  = blockIdx.y * 128;
    const int tid = threadIdx.x;
    const int warp = tid >> 5;
    const int wm = (warp >> 2) * 64;
    const int wn = (warp & 3) * 32;

    for (int i = tid; i < 16 * 128; i += 256) {
        int r = i >> 7, c = i & 127;
        BiasT[r * 132 + c] = bih[n0 + c] + bhh[n0 + c];
    }
    __syncthreads();

    wmma::fragment<wmma::accumulator, 16, 16, 8, float> cf[4][2];
#pragma unroll
    for (int i = 0; i < 4; i++)
#pragma unroll
        for (int j = 0; j < 2; j++)
            wmma::load_matrix_sync(cf[i][j], &BiasT[wn + j * 16], 132, wmma::mem_row_major);
    __syncthreads();

    for (int kt = 0; kt < 256; kt += 32) {
#pragma unroll
        for (int ld = 0; ld < 4; ld++) {
            int i = tid + ld * 256, row = i >> 3, kq = (i & 7) * 4;
            *reinterpret_cast<float4*>(&As[row * AP + kq]) =
                *reinterpret_cast<const float4*>(&A[(size_t)(m0 + row) * 256 + kt + kq]);
            *reinterpret_cast<float4*>(&Bs[row * AP + kq]) =
                *reinterpret_cast<const float4*>(&W[(size_t)(n0 + row) * 256 + kt + kq]);
        }
        __syncthreads();
#pragma unroll
        for (int kk = 0; kk < 32; kk += 8) {
            wmma::fragment<wmma::matrix_a, 16, 16, 8, wmma::precision::tf32, wmma::row_major> af[4];
            wmma::fragment<wmma::matrix_b, 16, 16, 8, wmma::precision::tf32, wmma::col_major> bf[2];
#pragma unroll
            for (int i = 0; i < 4; i++) {
                wmma::load_matrix_sync(af[i], &As[(wm + i * 16) * AP + kk], AP);
#pragma unroll
                for (int t = 0; t < af[i].num_elements; t++)
                    af[i].x[t] = wmma::__float_to_tf32(af[i].x[t]);
            }
#pragma unroll
            for (int j = 0; j < 2; j++) {
                wmma::load_matrix_sync(bf[j], &Bs[(wn + j * 16) * AP + kk], AP);
#pragma unroll
                for (int t = 0; t < bf[j].num_elements; t++)
                    bf[j].x[t] = wmma::__float_to_tf32(bf[j].x[t]);
            }
#pragma unroll
            for (int i = 0; i < 4; i++)
#pragma unroll
                for (int j = 0; j < 2; j++)
                    wmma::mma_sync(cf[i][j], af[i], bf[j], cf[i][j]);
        }
        __syncthreads();
    }
#pragma unroll
    for (int i = 0; i < 4; i++)
#pragma unroll
        for (int j = 0; j < 2; j++)
            wmma::store_matrix_sync(
                &g_xproj[(size_t)(m0 + wm + i * 16) * 512 + n0 + wn + j * 16],
                cf[i][j], 512, wmma::mem_row_major);
}

// ---------------------------------------------------------------------------
// mma.sync recurrence helpers
// ---------------------------------------------------------------------------
__device__ __forceinline__ uint32_t smem_u32(const void* p) {
    uint32_t a;
    asm("{ .reg .u64 t; cvta.to.shared.u64 t, %1; cvt.u32.u64 %0, t; }" : "=r"(a) : "l"(p));
    return a;
}
__device__ __forceinline__ void mma16816(float* c, const uint32_t* a, uint32_t b0, uint32_t b1) {
    asm volatile(
        "mma.sync.aligned.m16n8k16.row.col.f32.bf16.bf16.f32 "
        "{%0,%1,%2,%3}, {%4,%5,%6,%7}, {%8,%9}, {%0,%1,%2,%3};"
        : "+f"(c[0]), "+f"(c[1]), "+f"(c[2]), "+f"(c[3])
        : "r"(a[0]), "r"(a[1]), "r"(a[2]), "r"(a[3]), "r"(b0), "r"(b1));
}
__device__ __forceinline__ void ldmx4(uint32_t& r0, uint32_t& r1, uint32_t& r2, uint32_t& r3,
                                      uint32_t addr) {
    asm volatile("ldmatrix.sync.aligned.m8n8.x4.shared.b16 {%0,%1,%2,%3}, [%4];"
                 : "=r"(r0), "=r"(r1), "=r"(r2), "=r"(r3) : "r"(addr));
}
__device__ __forceinline__ unsigned short bfh(float v) { return __bfloat16_as_ushort(__float2bfloat16(v)); }
__device__ __forceinline__ float bfv(unsigned short u) { return __bfloat162float(__ushort_as_bfloat16(u)); }
__device__ __forceinline__ uint32_t pkbf(float2 f) {
    return ((uint32_t)bfh(f.y) << 16) | (uint32_t)bfh(f.x);
}
__device__ __forceinline__ float sigm(float x)   { return __fdividef(1.f, 1.f + __expf(-x)); }
__device__ __forceinline__ float tanhf_(float x) { float e = __expf(2.f * x); return 1.f - __fdividef(2.f, e + 1.f); }

// smem: W_lo 128KB, then two B-frag tiles (hi, lo) 2KB each
#define WLO_OFF  0
#define BHI_OFF  131072
#define BLO_OFF  133120
#define SMEM_TOT 135680

// write h into frag-major B tiles (hi + lo bf16 split)
__device__ __forceinline__ void write_h(char* smem, int e, int b, float h) {
    unsigned short hh = bfh(h);
    unsigned short hl = bfh(h - bfv(hh));
    int kt = e >> 4, kk = e & 15;
    int half = kk >> 3, tq = (kk & 7) >> 1, lo = kk & 1;
    uint32_t byte = (uint32_t)(kt * 64 + (b * 4 + tq) * 2 + half) * 4 + lo * 2;
    *reinterpret_cast<unsigned short*>(smem + BHI_OFF + byte) = hh;
    *reinterpret_cast<unsigned short*>(smem + BLO_OFF + byte) = hl;
}

// ---------------------------------------------------------------------------
// Kernel 2: LSTM recurrence via mma.sync, W_hi register-stationary.
// 32 CTAs x 8 batch, 256 threads (8 warps). Warp w owns gate rows
// {16w..16w+16} in each of the 4 gate blocks (i,f,g,o) -> epilogue is
// register-local. 3 MMA terms: Whi@hhi + Whi@hlo + Wlo@hhi.
// ---------------------------------------------------------------------------
__global__ __launch_bounds__(256, 1)
void lstm_rec_mma(const float* __restrict__ Whh,
                  const float* __restrict__ h0,
                  const float* __restrict__ c0,
                  float* __restrict__ out)
{
    extern __shared__ char smem[];
    const int tid = threadIdx.x;
    const int w   = tid >> 5;
    const int l   = tid & 31;
    const int bg0 = blockIdx.x * 8;

    // ---- W_lo -> smem (quad-blocked tiles for ldmatrix.x4) ----
    for (int idx = tid; idx < 512 * 32; idx += 256) {
        int r  = idx >> 5;
        int kq = (idx & 31) * 4;
        float4 v = *reinterpret_cast<const float4*>(&Whh[(size_t)r * 128 + kq]);
        float vv[4] = {v.x, v.y, v.z, v.w};
        int mt = r >> 7, wo = (r >> 4) & 7, rr16 = r & 15;
#pragma unroll
        for (int j = 0; j < 4; j++) {
            int k = kq + j;
            float lo = vv[j] - bfv(bfh(vv[j]));
            uint32_t byte = (uint32_t)(mt * 32768 + wo * 4096 + (k >> 4) * 512
                          + (((rr16 >> 3) & 1) + 2 * ((k >> 3) & 1)) * 128
                          + (r & 7) * 16 + (k & 7) * 2);
            *reinterpret_cast<unsigned short*>(smem + WLO_OFF + byte) = bfh(lo);
        }
    }

    // ---- W_hi A-fragments in registers: [4 gate][8 kt][4 regs] ----
    uint32_t ahi[4][8][4];
    {
        const int g = l >> 2, t2 = (l & 3) * 2;
#pragma unroll
        for (int mt = 0; mt < 4; mt++)
#pragma unroll
            for (int kt = 0; kt < 8; kt++) {
                int r0 = mt * 128 + w * 16 + g;
                int k0 = kt * 16 + t2;
                ahi[mt][kt][0] = pkbf(*reinterpret_cast<const float2*>(&Whh[(size_t)r0 * 128 + k0]));
                ahi[mt][kt][1] = pkbf(*reinterpret_cast<const float2*>(&Whh[(size_t)(r0 + 8) * 128 + k0]));
                ahi[mt][kt][2] = pkbf(*reinterpret_cast<const float2*>(&Whh[(size_t)r0 * 128 + k0 + 8]));
                ahi[mt][kt][3] = pkbf(*reinterpret_cast<const float2*>(&Whh[(size_t)(r0 + 8) * 128 + k0 + 8]));
            }
    }

    // ---- item coords (4 per lane) + state init ----
    int ee[4], bb[4];
    float creg[4];
#pragma unroll
    for (int r = 0; r < 4; r++) {
        ee[r] = w * 16 + (l >> 2) + 8 * (r >> 1);
        bb[r] = 2 * (l & 3) + (r & 1);
        float h = h0[(size_t)(bg0 + bb[r]) * 128 + ee[r]];
        creg[r] = c0[(size_t)(bg0 + bb[r]) * 128 + ee[r]];
        write_h(smem, ee[r], bb[r], h);
    }

    // acc init = xproj[0]
    float acc[4][4];
#pragma unroll
    for (int mt = 0; mt < 4; mt++)
#pragma unroll
        for (int r = 0; r < 4; r++)
            acc[mt][r] = g_xproj[((size_t)bg0 + bb[r]) * 512 + mt * 128 + ee[r]];

    const uint32_t sb = smem_u32(smem);
    const uint32_t wlo_lane = sb + WLO_OFF + (uint32_t)w * 4096
                            + (uint32_t)((l >> 3) * 128 + (l & 7) * 16);
    __syncthreads();

    for (int t = 0; t < T_STEPS; t++) {
        // prefetch next step's xproj (consumed after epilogue)
        float xpn[4][4];
        {
            int tn = (t + 1 < T_STEPS) ? t + 1 : t;
#pragma unroll
            for (int mt = 0; mt < 4; mt++)
#pragma unroll
                for (int r = 0; r < 4; r++)
                    xpn[mt][r] = __ldg(&g_xproj[((size_t)tn * BATCH + bg0 + bb[r]) * 512
                                                + mt * 128 + ee[r]]);
        }

        // ---- MMA phase: 3 terms ----
#pragma unroll
        for (int kt = 0; kt < 8; kt++) {
            uint2 vh = *reinterpret_cast<const uint2*>(smem + BHI_OFF + kt * 256 + l * 8);
            uint2 vl = *reinterpret_cast<const uint2*>(smem + BLO_OFF + kt * 256 + l * 8);
#pragma unroll
            for (int mt = 0; mt < 4; mt++) {
                uint32_t q[4];
                ldmx4(q[0], q[1], q[2], q[3], wlo_lane + mt * 32768 + kt * 512);
                mma16816(acc[mt], ahi[mt][kt], vh.x, vh.y);
                mma16816(acc[mt], ahi[mt][kt], vl.x, vl.y);
                mma16816(acc[mt], q, vh.x, vh.y);
            }
        }
        __syncthreads();   // all warps done reading B tiles

        // ---- epilogue: register-local gate fusion ----
#pragma unroll
        for (int r = 0; r < 4; r++) {
            float i_ = sigm(acc[0][r]);
            float f_ = sigm(acc[1][r]);
            float g_ = tanhf_(acc[2][r]);
            float o_ = sigm(acc[3][r]);
            creg[r] = f_ * creg[r] + i_ * g_;
            float h = o_ * tanhf_(creg[r]);
            write_h(smem, ee[r], bb[r], h);
            out[((size_t)t * BATCH + bg0 + bb[r]) * E_DIM + ee[r]] = log1pf(__expf(h));
        }
        // roll accumulators to next step's xproj
#pragma unroll
        for (int mt = 0; mt < 4; mt++)
#pragma unroll
            for (int r = 0; r < 4; r++)
                acc[mt][r] = xpn[mt][r];
        __syncthreads();   // B tiles ready for next step
    }
}

// ---------------------------------------------------------------------------
extern "C" void kernel_launch(void* const* d_in, const int* in_sizes, int n_in,
                              void* d_out, int out_size)
{
    const float* x   = (const float*)d_in[0];
    const float* h0  = (const float*)d_in[1];
    const float* c0  = (const float*)d_in[2];
    const float* Wih = (const float*)d_in[3];
    const float* Whh = (const float*)d_in[4];
    const float* bih = (const float*)d_in[5];
    const float* bhh = (const float*)d_in[6];
    float* out = (float*)d_out;

    cudaFuncSetAttribute((const void*)lstm_rec_mma,
                         cudaFuncAttributeMaxDynamicSharedMemorySize, SMEM_TOT);

    xproj_gemm_tf32<<<dim3(4, 2048), 256>>>(x, Wih, bih, bhh);
    lstm_rec_mma<<<32, 256, SMEM_TOT>>>(Whh, h0, c0, out);
}